// round 17
// baseline (speedup 1.0000x reference)
#include <cuda_runtime.h>
#include <cuda_bf16.h>
#include <math.h>

#define BB 4
#define CC 64
#define NN 4096
#define KK 16

__device__ float g_val_t[BB * NN * CC];
__device__ float g_key_t[BB * NN * CC];
__device__ float g_agg[BB * NN * CC];
__device__ int   g_idx[BB * NN * KK];

typedef unsigned long long ull;
typedef unsigned int uint32;

// ---- smem offsets. H1 (65536B) aliases U (16384) + THB (16384) + spare. ----
#define OFF_H1   1024
#define OFF_U    1024
#define OFF_THB  17408
#define OFF_A1   66560
#define OFF_A2   99328
#define OFF_P2B  132096
#define OFF_KEY  140288
#define OFF_P1P  175104
#define OFF_WQ   175872
#define OFF_B1P  176640
#define OFF_PB1P 177664
#define OFF_PB2S 177920
#define OFF_BQS  178176
#define OFF_S1S  178432
#define OFF_S2S  178688
#define OFF_POSR 179712
#define OFF_QY   181248
#define OFF_VALS 183296
#define SM_TOTAL 185344

#define CVTBF2(res, a, b) asm("cvt.rn.satfinite.bf16x2.f32 %0, %1, %2;" : "=r"(res) : "f"(b), "f"(a))

static __device__ __forceinline__ uint32 smem_u32(const void* p) {
    uint32 a;
    asm("{ .reg .u64 t; cvta.to.shared.u64 t, %1; cvt.u32.u64 %0, t; }" : "=r"(a) : "l"(p));
    return a;
}
static __device__ __forceinline__ void ldsm4(uint32& r0, uint32& r1, uint32& r2, uint32& r3, uint32 addr) {
    asm volatile("ldmatrix.sync.aligned.m8n8.x4.shared.b16 {%0,%1,%2,%3}, [%4];"
                 : "=r"(r0), "=r"(r1), "=r"(r2), "=r"(r3) : "r"(addr));
}
static __device__ __forceinline__ void mma16816(
    float& d0, float& d1, float& d2, float& d3,
    uint32 a0, uint32 a1, uint32 a2, uint32 a3, uint32 b0, uint32 b1)
{
    asm volatile(
        "mma.sync.aligned.m16n8k16.row.col.f32.bf16.bf16.f32 "
        "{%0,%1,%2,%3}, {%4,%5,%6,%7}, {%8,%9}, {%0,%1,%2,%3};"
        : "+f"(d0), "+f"(d1), "+f"(d2), "+f"(d3)
        : "r"(a0), "r"(a1), "r"(a2), "r"(a3), "r"(b0), "r"(b1));
}

__global__ void k_dummy() {}
__global__ void k_dummy2() {}

// ================= Kernel 1: linear_start + key (transposed outputs) =================
__global__ __launch_bounds__(256) void k_linear_start_key(
    const float* __restrict__ y,
    const float* __restrict__ Ws_g, const float* __restrict__ bs_g,
    const float* __restrict__ Wk_g, const float* __restrict__ bk_g)
{
    __shared__ float ys[64][64];
    __shared__ float y1s[64][64];
    __shared__ float Ws[64][64];
    int b = blockIdx.y, n0 = blockIdx.x * 64, t = threadIdx.x;
#pragma unroll
    for (int i = 0; i < 16; i++) { int e = t + i * 256; Ws[e >> 6][e & 63] = Ws_g[e]; }
#pragma unroll
    for (int i = 0; i < 16; i++) {
        int e = t + i * 256; int c = e >> 6, p = e & 63;
        ys[c][p] = y[((size_t)b * CC + c) * NN + n0 + p];
    }
    __syncthreads();
    int p = t & 63, og = t >> 6;
    float acc[16];
#pragma unroll
    for (int i = 0; i < 16; i++) acc[i] = bs_g[og * 16 + i];
#pragma unroll 4
    for (int c = 0; c < 64; c++) {
        float yv = ys[c][p];
#pragma unroll
        for (int i = 0; i < 16; i++) acc[i] = fmaf(Ws[og * 16 + i][c], yv, acc[i]);
    }
#pragma unroll
    for (int i = 0; i < 16; i++) y1s[og * 16 + i][p] = acc[i];
    {
        float4* vo = (float4*)&g_val_t[(((size_t)b * NN) + n0 + p) * CC + og * 16];
        vo[0] = make_float4(acc[0], acc[1], acc[2], acc[3]);
        vo[1] = make_float4(acc[4], acc[5], acc[6], acc[7]);
        vo[2] = make_float4(acc[8], acc[9], acc[10], acc[11]);
        vo[3] = make_float4(acc[12], acc[13], acc[14], acc[15]);
    }
    __syncthreads();
#pragma unroll
    for (int i = 0; i < 16; i++) { int e = t + i * 256; Ws[e >> 6][e & 63] = Wk_g[e]; }
    __syncthreads();
#pragma unroll
    for (int i = 0; i < 16; i++) acc[i] = bk_g[og * 16 + i];
#pragma unroll 4
    for (int c = 0; c < 64; c++) {
        float yv = y1s[c][p];
#pragma unroll
        for (int i = 0; i < 16; i++) acc[i] = fmaf(Ws[og * 16 + i][c], yv, acc[i]);
    }
    {
        float4* ko = (float4*)&g_key_t[(((size_t)b * NN) + n0 + p) * CC + og * 16];
        ko[0] = make_float4(acc[0], acc[1], acc[2], acc[3]);
        ko[1] = make_float4(acc[4], acc[5], acc[6], acc[7]);
        ko[2] = make_float4(acc[8], acc[9], acc[10], acc[11]);
        ko[3] = make_float4(acc[12], acc[13], acc[14], acc[15]);
    }
}

// ================= Kernel 2: warp-per-query KNN with bitonic shfl merge =================
__device__ __forceinline__ void knn_insert(float d, int jc, float* bd, int* bi) {
    bool pr[16];
#pragma unroll
    for (int s = 0; s < 16; s++) pr[s] = d < bd[s];
#pragma unroll
    for (int s = 15; s >= 1; --s) {
        bd[s] = pr[s - 1] ? bd[s - 1] : (pr[s] ? d : bd[s]);
        bi[s] = pr[s - 1] ? bi[s - 1] : (pr[s] ? jc : bi[s]);
    }
    bd[0] = pr[0] ? d : bd[0];
    bi[0] = pr[0] ? jc : bi[0];
}

__global__ __launch_bounds__(256) void k_knn(const float* __restrict__ x)
{
    __shared__ float4 cand[256];
    int b = blockIdx.y;
    int w = threadIdx.x >> 5, lane = threadIdx.x & 31;
    int i = blockIdx.x * 8 + w;                 // this warp's query
    const float* xb = x + (size_t)b * 3 * NN;
    float qx = xb[i], qy = xb[NN + i], qz = xb[2 * NN + i];

    float bd[16]; int bi[16];
#pragma unroll
    for (int s = 0; s < 16; s++) { bd[s] = 3.0e38f; bi[s] = 0; }

    // scan: lane handles candidates ≡ lane (mod 32); per-lane sorted top-16
    for (int c0 = 0; c0 < NN; c0 += 256) {
        int j = c0 + threadIdx.x;
        float ax = xb[j], ay = xb[NN + j], az = xb[2 * NN + j];
        cand[threadIdx.x] = make_float4(ax, ay, az, ax * ax + ay * ay + az * az);
        __syncthreads();
#pragma unroll
        for (int u = 0; u < 8; u++) {
            float4 cv = cand[u * 32 + lane];
            float d = fmaf(-2.0f, qx * cv.x + qy * cv.y + qz * cv.z, cv.w);
            if (d < bd[15]) knn_insert(d, c0 + u * 32 + lane, bd, bi);
        }
        __syncthreads();
    }

    // warp-wide bitonic top-16 merge (5 rounds of shfl_xor)
#pragma unroll
    for (int off = 1; off < 32; off <<= 1) {
        float od[16]; int oi[16];
#pragma unroll
        for (int s = 0; s < 16; s++) {
            od[s] = __shfl_xor_sync(0xFFFFFFFFu, bd[s], off);
            oi[s] = __shfl_xor_sync(0xFFFFFFFFu, bi[s], off);
        }
        // keep lowest 16 of (mine asc, partner asc): C[s] = min(A[s], B[15-s]) -> bitonic
#pragma unroll
        for (int s = 0; s < 16; s++) {
            float o = od[15 - s]; int io = oi[15 - s];
            if (o < bd[s]) { bd[s] = o; bi[s] = io; }
        }
        // bitonic cleanup: stages k = 8,4,2,1
#pragma unroll
        for (int k = 8; k >= 1; k >>= 1) {
#pragma unroll
            for (int s = 0; s < 16; s++) {
                if ((s & k) == 0) {
                    int sp = s + k;
                    if (bd[sp] < bd[s]) {
                        float td = bd[s]; bd[s] = bd[sp]; bd[sp] = td;
                        int ti = bi[s]; bi[s] = bi[sp]; bi[sp] = ti;
                    }
                }
            }
        }
    }
    if (lane == 0) {
#pragma unroll
        for (int s = 0; s < 16; s++) g_idx[((size_t)b * NN + i) * KK + s] = bi[s];
    }
}

// ================= Kernel 3: full-mma fused attention (8-pt tiles) — R13/R15 verbatim =================
#define NTILES (BB * NN / 8)

__global__ void __launch_bounds__(256, 1) k_attn(
    const float* __restrict__ x,
    const float* __restrict__ Wq_g, const float* __restrict__ bq_g,
    const float* __restrict__ P1, const float* __restrict__ pb1,
    const float* __restrict__ bn1_g, const float* __restrict__ bn1_b,
    const float* __restrict__ bn1_m, const float* __restrict__ bn1_v,
    const float* __restrict__ P2, const float* __restrict__ pb2,
    const float* __restrict__ A1, const float* __restrict__ ab1,
    const float* __restrict__ bn2_g, const float* __restrict__ bn2_b,
    const float* __restrict__ bn2_m, const float* __restrict__ bn2_v,
    const float* __restrict__ A2, const float* __restrict__ ab2)
{
    extern __shared__ char sm[];
    const int t = threadIdx.x;
    const uint32 smb = smem_u32(sm);

    float* s_key  = (float*)(sm + OFF_KEY);
    float* s_p1p  = (float*)(sm + OFF_P1P);
    float* s_wq   = (float*)(sm + OFF_WQ);
    float* s_b1p  = (float*)(sm + OFF_B1P);
    float* s_pb1p = (float*)(sm + OFF_PB1P);
    float* s_pb2  = (float*)(sm + OFF_PB2S);
    float* s_bqs  = (float*)(sm + OFF_BQS);
    float* s_s1   = (float*)(sm + OFF_S1S);
    float* s_s2   = (float*)(sm + OFF_S2S);
    float* s_posr = (float*)(sm + OFF_POSR);
    float* s_qy   = (float*)(sm + OFF_QY);
    float* s_vals = (float*)(sm + OFF_VALS);

    {
        float s2 = bn2_g[t] * rsqrtf(bn2_v[t] + 1e-5f);
        s_s2[t] = s2;
        s_b1p[t] = (ab1[t] - bn2_m[t]) * s2 + bn2_b[t];
    }
    if (t < 64) {
        float s1 = bn1_g[t] * rsqrtf(bn1_v[t] + 1e-5f);
        s_s1[t] = s1;
        s_pb1p[t] = (pb1[t] - bn1_m[t]) * s1 + bn1_b[t];
        s_pb2[t] = pb2[t];
        s_bqs[t] = bq_g[t];
    }
    if (t < 192) s_wq[t] = Wq_g[t];
    __syncthreads();
    if (t < 192) s_p1p[t] = P1[t] * s_s1[t / 3];
#pragma unroll
    for (int i = 0; i < 64; i++) {
        int idx = t + i * 256; int a = idx >> 6, c = idx & 63;
        *(__nv_bfloat16*)(sm + OFF_A1 + a * 128 + ((c * 2) ^ ((a & 7) << 4))) =
            __float2bfloat16(A1[idx] * s_s2[a]);
    }
#pragma unroll
    for (int i = 0; i < 64; i++) {
        int idx = t + i * 256; int c = idx >> 8, h = idx & 255;
        *(__nv_bfloat16*)(sm + OFF_A2 + c * 512 + ((h * 2) ^ ((c & 7) << 4))) =
            __float2bfloat16(A2[idx]);
    }
#pragma unroll
    for (int i = 0; i < 16; i++) {
        int idx = t + i * 256; int c = idx >> 6, h = idx & 63;
        *(__nv_bfloat16*)(sm + OFF_P2B + c * 128 + ((h * 2) ^ ((c & 7) << 4))) =
            __float2bfloat16(P2[idx]);
    }
    __syncthreads();

    const int lane = t & 31, w = t >> 5;
    const int g = lane >> 2, tig = lane & 3;
    const int e0 = w * 16;
    const int ar = lane & 15;
    const int acb = (lane >> 4) << 3;
    const int br = (lane & 7) + ((lane >> 4) << 3);
    const int bkb = (lane & 8) ? 8 : 0;
    const uint32 swsA = (uint32)((lane & 7) << 4);
    const uint32 aU_base  = smb + OFF_U   + (uint32)(e0 + ar) * 128;
    const uint32 aTH_base = smb + OFF_THB + (uint32)(e0 + ar) * 128;
    const uint32 aH_base  = smb + OFF_H1  + (uint32)(e0 + ar) * 512;
    const uint32 bA1_base = smb + OFF_A1  + (uint32)br * 128;
    const uint32 bA2_base = smb + OFF_A2  + (uint32)br * 512;
    const uint32 bP2_base = smb + OFF_P2B + (uint32)br * 128;

    for (int tile = blockIdx.x; tile < NTILES; tile += gridDim.x) {
        int b = tile >> 9;
        int n0 = (tile & 511) * 8;
        const float* xb = x + (size_t)b * 3 * NN;
        const int* idxb = &g_idx[(size_t)b * NN * KK];

        {
            int e = t & 127, cq = t >> 7;
            int pt = e >> 4, k = e & 15;
            int j = idxb[(n0 + pt) * KK + k];
            const float4* kp = (const float4*)&g_key_t[((size_t)b * NN + j) * CC + cq * 32];
            float* kd = &s_key[e * 68 + cq * 32];
#pragma unroll
            for (int q = 0; q < 8; q++) *(float4*)&kd[q * 4] = kp[q];
        }
        if (t < 128) {
            int pt = t >> 4, k = t & 15;
            int j = idxb[(n0 + pt) * KK + k];
#pragma unroll
            for (int d = 0; d < 3; d++)
                s_posr[(pt * 3 + d) * 16 + k] = xb[d * NN + n0 + pt] - xb[d * NN + j];
        }
        {
            int c6 = t & 63;
#pragma unroll
            for (int ss = 0; ss < 2; ss++) {
                int pt = (t >> 6) + ss * 4;
                int n = n0 + pt;
                s_qy[pt * 64 + c6] = s_bqs[c6] + s_wq[c6 * 3] * xb[n]
                    + s_wq[c6 * 3 + 1] * xb[NN + n] + s_wq[c6 * 3 + 2] * xb[2 * NN + n];
                s_vals[pt * 64 + c6] = g_val_t[((size_t)b * NN + n) * CC + c6];
            }
        }
        __syncthreads();

        {
            int e = t >> 1, h0 = (t & 1) * 32;
            int pt = e >> 4, k = e & 15;
            const float* pr = &s_posr[pt * 48];
            float px = pr[k], py = pr[16 + k], pz = pr[32 + k];
            uint32 sw = (uint32)((e & 7) << 4);
#pragma unroll
            for (int q = 0; q < 4; q++) {
                uint32 pk[4];
#pragma unroll
                for (int ii = 0; ii < 4; ii++) {
                    int h = h0 + q * 8 + ii * 2;
                    float f0 = fmaxf(s_pb1p[h] + s_p1p[h * 3] * px
                            + s_p1p[h * 3 + 1] * py + s_p1p[h * 3 + 2] * pz, 0.0f);
                    float f1 = fmaxf(s_pb1p[h + 1] + s_p1p[h * 3 + 3] * px
                            + s_p1p[h * 3 + 4] * py + s_p1p[h * 3 + 5] * pz, 0.0f);
                    CVTBF2(pk[ii], f0, f1);
                }
                *(uint4*)(sm + OFF_THB + e * 128 + (((uint32)((h0 + q * 8) * 2)) ^ sw)) = *(uint4*)pk;
            }
        }
        __syncwarp();

        float PE[8][4];
#pragma unroll
        for (int nt = 0; nt < 8; nt++)
#pragma unroll
            for (int q = 0; q < 4; q++) PE[nt][q] = 0.0f;
#pragma unroll
        for (int kk = 0; kk < 4; kk++) {
            uint32 A0, A1r, A2r, A3;
            ldsm4(A0, A1r, A2r, A3, aTH_base + (((uint32)((kk * 16 + acb) * 2)) ^ swsA));
#pragma unroll
            for (int ntp = 0; ntp < 4; ntp++) {
                uint32 b0, b1, b2, b3;
                ldsm4(b0, b1, b2, b3,
                      bP2_base + (uint32)((ntp * 16) * 128)
                               + (((uint32)((kk * 16 + bkb) * 2)) ^ swsA));
                mma16816(PE[ntp * 2][0], PE[ntp * 2][1], PE[ntp * 2][2], PE[ntp * 2][3],
                         A0, A1r, A2r, A3, b0, b1);
                mma16816(PE[ntp * 2 + 1][0], PE[ntp * 2 + 1][1], PE[ntp * 2 + 1][2], PE[ntp * 2 + 1][3],
                         A0, A1r, A2r, A3, b2, b3);
            }
        }
        {
            int row0 = e0 + g, row1 = e0 + 8 + g;
#pragma unroll
            for (int nt = 0; nt < 8; nt++) {
                int c0 = nt * 8 + 2 * tig;
                float pb0 = s_pb2[c0], pb1v = s_pb2[c0 + 1];
                PE[nt][0] += pb0; PE[nt][1] += pb1v;
                PE[nt][2] += pb0; PE[nt][3] += pb1v;
                float2 qv = *(const float2*)&s_qy[w * 64 + c0];
                float2 kA = *(const float2*)&s_key[row0 * 68 + c0];
                float2 kB = *(const float2*)&s_key[row1 * 68 + c0];
                float u00 = (qv.x - kA.x) + PE[nt][0];
                float u01 = (qv.y - kA.y) + PE[nt][1];
                float u10 = (qv.x - kB.x) + PE[nt][2];
                float u11 = (qv.y - kB.y) + PE[nt][3];
                uint32 p0, p1;
                CVTBF2(p0, u00, u01);
                CVTBF2(p1, u10, u11);
                uint32 co = ((uint32)(c0 * 2)) ^ ((uint32)(g << 4));
                *(uint32*)(sm + OFF_U + row0 * 128 + co) = p0;
                *(uint32*)(sm + OFF_U + row1 * 128 + co) = p1;
            }
        }
        __syncwarp();

        uint32 AU[4][4];
#pragma unroll
        for (int kk = 0; kk < 4; kk++)
            ldsm4(AU[kk][0], AU[kk][1], AU[kk][2], AU[kk][3],
                  aU_base + (((uint32)((kk * 16 + acb) * 2)) ^ swsA));
        __syncthreads();

#pragma unroll
        for (int chunk = 0; chunk < 4; chunk++) {
            float acc[8][4];
#pragma unroll
            for (int nt = 0; nt < 8; nt++)
#pragma unroll
                for (int q = 0; q < 4; q++) acc[nt][q] = 0.0f;
#pragma unroll
            for (int kk = 0; kk < 4; kk++) {
#pragma unroll
                for (int ntp = 0; ntp < 4; ntp++) {
                    uint32 b0, b1, b2, b3;
                    ldsm4(b0, b1, b2, b3,
                          bA1_base + (uint32)((chunk * 64 + ntp * 16) * 128)
                                   + (((uint32)((kk * 16 + bkb) * 2)) ^ swsA));
                    mma16816(acc[ntp * 2][0], acc[ntp * 2][1], acc[ntp * 2][2], acc[ntp * 2][3],
                             AU[kk][0], AU[kk][1], AU[kk][2], AU[kk][3], b0, b1);
                    mma16816(acc[ntp * 2 + 1][0], acc[ntp * 2 + 1][1], acc[ntp * 2 + 1][2], acc[ntp * 2 + 1][3],
                             AU[kk][0], AU[kk][1], AU[kk][2], AU[kk][3], b2, b3);
                }
            }
            int row0 = e0 + g, row1 = e0 + 8 + g;
            uint32 swg = (uint32)(g << 4);
#pragma unroll
            for (int nt = 0; nt < 8; nt++) {
                int a0 = chunk * 64 + nt * 8 + 2 * tig;
                float b0v = s_b1p[a0], b1v = s_b1p[a0 + 1];
                float h00 = fmaxf(acc[nt][0] + b0v, 0.0f);
                float h01 = fmaxf(acc[nt][1] + b1v, 0.0f);
                float h10 = fmaxf(acc[nt][2] + b0v, 0.0f);
                float h11 = fmaxf(acc[nt][3] + b1v, 0.0f);
                uint32 p0, p1;
                CVTBF2(p0, h00, h01);
                CVTBF2(p1, h10, h11);
                uint32 co = ((uint32)(a0 * 2)) ^ swg;
                *(uint32*)(sm + OFF_H1 + row0 * 512 + co) = p0;
                *(uint32*)(sm + OFF_H1 + row1 * 512 + co) = p1;
            }
        }
        __syncwarp();

        float ac2[8][4];
#pragma unroll
        for (int nt = 0; nt < 8; nt++)
#pragma unroll
            for (int q = 0; q < 4; q++) ac2[nt][q] = 0.0f;
#pragma unroll 4
        for (int kk = 0; kk < 16; kk++) {
            uint32 A0, A1r, A2r, A3;
            ldsm4(A0, A1r, A2r, A3, aH_base + (((uint32)((kk * 16 + acb) * 2)) ^ swsA));
#pragma unroll
            for (int ntp = 0; ntp < 4; ntp++) {
                uint32 b0, b1, b2, b3;
                ldsm4(b0, b1, b2, b3,
                      bA2_base + (uint32)((ntp * 16) * 512)
                               + (((uint32)((kk * 16 + bkb) * 2)) ^ swsA));
                mma16816(ac2[ntp * 2][0], ac2[ntp * 2][1], ac2[ntp * 2][2], ac2[ntp * 2][3],
                         A0, A1r, A2r, A3, b0, b1);
                mma16816(ac2[ntp * 2 + 1][0], ac2[ntp * 2 + 1][1], ac2[ntp * 2 + 1][2], ac2[ntp * 2 + 1][3],
                         A0, A1r, A2r, A3, b2, b3);
            }
        }

        {
            size_t orow = ((size_t)b * NN + n0 + w) * CC;
#pragma unroll
            for (int nt = 0; nt < 8; nt++) {
                int c0 = nt * 8 + 2 * tig;
                float ex0 = __expf(ac2[nt][0]);
                float ex1 = __expf(ac2[nt][1]);
                float ex2 = __expf(ac2[nt][2]);
                float ex3 = __expf(ac2[nt][3]);
                float sv0 = ex0 + ex2, sv1 = ex1 + ex3;
                float tv0 = ex0 * PE[nt][0] + ex2 * PE[nt][2];
                float tv1 = ex1 * PE[nt][1] + ex3 * PE[nt][3];
                sv0 += __shfl_xor_sync(0xFFFFFFFFu, sv0, 4);
                sv1 += __shfl_xor_sync(0xFFFFFFFFu, sv1, 4);
                tv0 += __shfl_xor_sync(0xFFFFFFFFu, tv0, 4);
                tv1 += __shfl_xor_sync(0xFFFFFFFFu, tv1, 4);
                sv0 += __shfl_xor_sync(0xFFFFFFFFu, sv0, 8);
                sv1 += __shfl_xor_sync(0xFFFFFFFFu, sv1, 8);
                tv0 += __shfl_xor_sync(0xFFFFFFFFu, tv0, 8);
                tv1 += __shfl_xor_sync(0xFFFFFFFFu, tv1, 8);
                sv0 += __shfl_xor_sync(0xFFFFFFFFu, sv0, 16);
                sv1 += __shfl_xor_sync(0xFFFFFFFFu, sv1, 16);
                tv0 += __shfl_xor_sync(0xFFFFFFFFu, tv0, 16);
                tv1 += __shfl_xor_sync(0xFFFFFFFFu, tv1, 16);
                if (lane < 4) {
                    g_agg[orow + c0]     = s_vals[w * 64 + c0] + __fdividef(tv0, sv0);
                    g_agg[orow + c0 + 1] = s_vals[w * 64 + c0 + 1] + __fdividef(tv1, sv1);
                }
            }
        }
        __syncthreads();
    }
}

// ================= Kernel 4: out = W_end @ agg + b_end + y =================
__global__ __launch_bounds__(256) void k_end(
    const float* __restrict__ y, const float* __restrict__ We_g,
    const float* __restrict__ be_g, float* __restrict__ out)
{
    __shared__ float As[64][65];
    __shared__ float Ws[64][64];
    int b = blockIdx.y, n0 = blockIdx.x * 64, t = threadIdx.x;
#pragma unroll
    for (int i = 0; i < 16; i++) { int e = t + i * 256; Ws[e >> 6][e & 63] = We_g[e]; }
#pragma unroll
    for (int i = 0; i < 16; i++) {
        int e = t + i * 256; int p = e >> 6, c = e & 63;
        As[p][c] = g_agg[((size_t)b * NN + n0 + p) * CC + c];
    }
    __syncthreads();
    int p = t & 63, og = t >> 6;
    float acc[16];
#pragma unroll
    for (int i = 0; i < 16; i++) acc[i] = be_g[og * 16 + i];
#pragma unroll 4
    for (int c = 0; c < 64; c++) {
        float av = As[p][c];
#pragma unroll
        for (int i = 0; i < 16; i++) acc[i] = fmaf(Ws[og * 16 + i][c], av, acc[i]);
    }
#pragma unroll
    for (int i = 0; i < 16; i++) {
        int o = og * 16 + i;
        size_t off = ((size_t)b * CC + o) * NN + n0 + p;
        out[off] = acc[i] + y[off];
    }
}

// ================= launcher (k_knn is 4th launch -> profiled) =================
extern "C" void kernel_launch(void* const* d_in, const int* in_sizes, int n_in,
                              void* d_out, int out_size)
{
    const float* x       = (const float*)d_in[0];
    const float* y       = (const float*)d_in[1];
    const float* W_start = (const float*)d_in[2];
    const float* b_start = (const float*)d_in[3];
    const float* W_key   = (const float*)d_in[4];
    const float* b_key   = (const float*)d_in[5];
    const float* W_query = (const float*)d_in[6];
    const float* b_query = (const float*)d_in[7];
    const float* P1      = (const float*)d_in[8];
    const float* pb1     = (const float*)d_in[9];
    const float* bn1_g   = (const float*)d_in[10];
    const float* bn1_b   = (const float*)d_in[11];
    const float* bn1_m   = (const float*)d_in[12];
    const float* bn1_v   = (const float*)d_in[13];
    const float* P2      = (const float*)d_in[14];
    const float* pb2     = (const float*)d_in[15];
    const float* A1      = (const float*)d_in[16];
    const float* ab1     = (const float*)d_in[17];
    const float* bn2_g   = (const float*)d_in[18];
    const float* bn2_b   = (const float*)d_in[19];
    const float* bn2_m   = (const float*)d_in[20];
    const float* bn2_v   = (const float*)d_in[21];
    const float* A2      = (const float*)d_in[22];
    const float* ab2     = (const float*)d_in[23];
    const float* W_end   = (const float*)d_in[24];
    const float* b_end   = (const float*)d_in[25];

    cudaFuncSetAttribute(k_attn, cudaFuncAttributeMaxDynamicSharedMemorySize, SM_TOTAL);

    k_dummy<<<1, 32>>>();                                                                // 1
    k_linear_start_key<<<dim3(NN / 64, BB), 256>>>(y, W_start, b_start, W_key, b_key);   // 2
    k_dummy2<<<1, 32>>>();                                                               // 3
    k_knn<<<dim3(NN / 8, BB), 256>>>(x);                                                 // 4 <- profiled
    k_attn<<<148, 256, SM_TOTAL>>>(x, W_query, b_query,
                                   P1, pb1, bn1_g, bn1_b, bn1_m, bn1_v,
                                   P2, pb2, A1, ab1,
                                   bn2_g, bn2_b, bn2_m, bn2_v, A2, ab2);                 // 5
    k_end<<<dim3(NN / 64, BB), 256>>>(y, W_end, b_end, (float*)d_out);                   // 6
}